// round 11
// baseline (speedup 1.0000x reference)
#include <cuda_runtime.h>
#include <cuda_bf16.h>
#include <cstdint>

#define N_NODES 10000
#define E_EDGES 160000
#define IN_CH   14
#define HID     128
#define HEADS   8
#define OUT_CH  4
#define FEAT    (HEADS*HID)   // 1024

// ---------------- scratch (static device memory; no allocations) ----------------
__device__ float g_bufA[(size_t)N_NODES * FEAT];
__device__ float g_bufB[(size_t)N_NODES * FEAT];
__device__ float g_W2T[(size_t)FEAT * FEAT];
__device__ float g_als[N_NODES * HEADS];
__device__ float g_ald[N_NODES * HEADS];
__device__ float g_h3[N_NODES * OUT_CH];
__device__ float g_als3[N_NODES];
__device__ float g_ald3[N_NODES];
__device__ int   g_deg[N_NODES];
__device__ int   g_cursor[N_NODES];
__device__ int   g_rowptr[N_NODES + 1];
__device__ int   g_srcs[E_EDGES];
__device__ int   g_is64;

// ---------------- small PTX helpers ----------------
__device__ __forceinline__ uint32_t smem_u32(const void* p) {
    uint32_t a;
    asm("{ .reg .u64 t; cvta.to.shared.u64 t, %1; cvt.u32.u64 %0, t; }" : "=r"(a) : "l"(p));
    return a;
}

__device__ __forceinline__ void cp_async16(uint32_t s, const void* g, bool pred) {
    int sz = pred ? 16 : 0;
    asm volatile("cp.async.cg.shared.global [%0], [%1], 16, %2;\n"
                 :: "r"(s), "l"(g), "r"(sz) : "memory");
}
#define CP_COMMIT()  asm volatile("cp.async.commit_group;" ::: "memory")
#define CP_WAIT0()   asm volatile("cp.async.wait_group 0;" ::: "memory")

__device__ __forceinline__ uint32_t f2tf32(float f) {
    uint32_t r;
    asm("cvt.rna.tf32.f32 %0, %1;" : "=r"(r) : "f"(f));
    return r;
}

__device__ __forceinline__ void mma_tf32(float* c, const uint32_t* a, uint32_t b0, uint32_t b1) {
    asm volatile(
        "mma.sync.aligned.m16n8k8.row.col.f32.tf32.tf32.f32 "
        "{%0,%1,%2,%3}, {%4,%5,%6,%7}, {%8,%9}, {%0,%1,%2,%3};"
        : "+f"(c[0]), "+f"(c[1]), "+f"(c[2]), "+f"(c[3])
        : "r"(a[0]), "r"(a[1]), "r"(a[2]), "r"(a[3]), "r"(b0), "r"(b1));
}

__device__ __forceinline__ float leaky(float e) {
    return e > 0.f ? e : 0.2f * e;
}

// ---------------- edge index access (int32 vs int64 detected at runtime) --------
__device__ __forceinline__ int edge_val(const void* idx, int is64, long i) {
    if (is64) return (int)((const long long*)idx)[i];
    return ((const int*)idx)[i];
}

// ---------------- CSR build ----------------
// zero + edge-width detection fused
__global__ void zero_kernel(const int* p) {
    int i = blockIdx.x * blockDim.x + threadIdx.x;
    if (i < N_NODES) { g_deg[i] = 0; g_cursor[i] = 0; }
    if (blockIdx.x == 0 && threadIdx.x == 0) {
        int is64 = 1;
        for (int k = 0; k < 64; k++) {
            if (p[2*k + 1] != 0) { is64 = 0; break; }
        }
        g_is64 = is64;
    }
}

__global__ void count_kernel(const void* idx) {
    int e = blockIdx.x * blockDim.x + threadIdx.x;
    if (e < E_EDGES) {
        int f = g_is64;
        int d = edge_val(idx, f, (long)E_EDGES + e);
        atomicAdd(&g_deg[d], 1);
    }
}

// shuffle-based scan: 1024 threads, 10 elems/thread, 2 barriers
__global__ void scan_kernel() {
    __shared__ int wsum[32];
    int t = threadIdx.x, lane = t & 31, w = t >> 5;
    const int CH = (N_NODES + 1023) / 1024;  // 10
    int base = t * CH;
    int s = 0;
#pragma unroll
    for (int i = 0; i < CH; i++) {
        int idx = base + i;
        if (idx < N_NODES) s += g_deg[idx];
    }
    int v = s;
#pragma unroll
    for (int off = 1; off < 32; off <<= 1) {
        int u = __shfl_up_sync(~0u, v, off);
        if (lane >= off) v += u;
    }
    if (lane == 31) wsum[w] = v;
    __syncthreads();
    if (w == 0) {
        int x = wsum[lane];
#pragma unroll
        for (int off = 1; off < 32; off <<= 1) {
            int u = __shfl_up_sync(~0u, x, off);
            if (lane >= off) x += u;
        }
        wsum[lane] = x;
    }
    __syncthreads();
    int excl = v - s + (w > 0 ? wsum[w - 1] : 0);
    int run = excl;
#pragma unroll
    for (int i = 0; i < CH; i++) {
        int idx = base + i;
        if (idx < N_NODES) { g_rowptr[idx] = run; run += g_deg[idx]; }
    }
    if (t == 1023) g_rowptr[N_NODES] = run;
}

__global__ void scatter_kernel(const void* idx) {
    int e = blockIdx.x * blockDim.x + threadIdx.x;
    if (e < E_EDGES) {
        int f = g_is64;
        int s = edge_val(idx, f, e);
        int d = edge_val(idx, f, (long)E_EDGES + e);
        int pos = g_rowptr[d] + atomicAdd(&g_cursor[d], 1);
        g_srcs[pos] = s;
    }
}

// ---------------- Layer-1 GEMM + fused attention logits ----------------
// [N,14] @ [14,1024] with h staged in smem; als/ald computed in-block.
#define G1N 16
__global__ __launch_bounds__(256) void gemm1_kernel(const float* __restrict__ x,
                                                    const float* __restrict__ W1,
                                                    const float* __restrict__ asrc,
                                                    const float* __restrict__ adst,
                                                    float* __restrict__ h,
                                                    float* __restrict__ als,
                                                    float* __restrict__ ald) {
    extern __shared__ float hs[];            // G1N * FEAT floats (64 KB)
    __shared__ float xs[G1N * IN_CH];
    int nb = blockIdx.x * G1N;
    int t = threadIdx.x;
    if (t < G1N * IN_CH) xs[t] = x[nb * IN_CH + t];
    __syncthreads();
#pragma unroll
    for (int j = 0; j < 4; j++) {
        int c = t + j * 256;
        float w[IN_CH];
#pragma unroll
        for (int k = 0; k < IN_CH; k++) w[k] = W1[k * FEAT + c];
        for (int n = 0; n < G1N; n++) {
            float acc = 0.f;
#pragma unroll
            for (int k = 0; k < IN_CH; k++) acc += xs[n * IN_CH + k] * w[k];
            hs[n * FEAT + c] = acc;
            h[(size_t)(nb + n) * FEAT + c] = acc;
        }
    }
    __syncthreads();
    // fused logits: warp w = head w
    int wd = t >> 5, lane = t & 31;
    float4 sa = *(const float4*)&asrc[wd * HID + lane * 4];
    float4 da = *(const float4*)&adst[wd * HID + lane * 4];
    for (int n = 0; n < G1N; n++) {
        float4 hv = *(const float4*)&hs[n * FEAT + wd * HID + lane * 4];
        float ss = hv.x * sa.x + hv.y * sa.y + hv.z * sa.z + hv.w * sa.w;
        float sd = hv.x * da.x + hv.y * da.y + hv.z * da.z + hv.w * da.w;
#pragma unroll
        for (int off = 16; off; off >>= 1) {
            ss += __shfl_xor_sync(~0u, ss, off);
            sd += __shfl_xor_sync(~0u, sd, off);
        }
        if (lane == 0) {
            als[(nb + n) * HEADS + wd] = ss;
            ald[(nb + n) * HEADS + wd] = sd;
        }
    }
}

// ---------------- W2 transpose + tf32 pre-round: W2T[n][k] = rna(W2[k][n]) -------
__global__ __launch_bounds__(256) void transpose_kernel(const float* __restrict__ W,
                                                        float* __restrict__ WT) {
    __shared__ float t[32][33];
    int bx = blockIdx.x * 32, by = blockIdx.y * 32;
    int x = bx + threadIdx.x;
    int y = by + threadIdx.y;
#pragma unroll
    for (int j = 0; j < 32; j += 8) t[threadIdx.y + j][threadIdx.x] = W[(size_t)(y + j) * FEAT + x];
    __syncthreads();
    int x2 = by + threadIdx.x;
    int y2 = bx + threadIdx.y;
#pragma unroll
    for (int j = 0; j < 32; j += 8)
        WT[(size_t)(y2 + j) * FEAT + x2] = __uint_as_float(f2tf32(t[threadIdx.x][threadIdx.y + j]));
}

// ---------------- zero als/ald before GEMM2 atomic epilogue ----------------
__global__ void zero_als_kernel(float* __restrict__ als, float* __restrict__ ald) {
    int i = blockIdx.x * blockDim.x + threadIdx.x;
    if (i < N_NODES * HEADS) { als[i] = 0.f; ald[i] = 0.f; }
}

// ---------------- fused per-node softmax + aggregate (heads=8, C=128) -----------
// round_out != 0: store tf32-rounded output (bit-identical to in-GEMM rounding)
// fuse3 != 0: instead of writing out, project through W3 and emit h3/als3/ald3
__global__ __launch_bounds__(256) void agg_kernel(const float* __restrict__ h,
                                                  const float* __restrict__ als,
                                                  const float* __restrict__ ald,
                                                  const float* __restrict__ bias,
                                                  float* __restrict__ out,
                                                  int round_out, int fuse3,
                                                  const float* __restrict__ W3,
                                                  const float* __restrict__ as3,
                                                  const float* __restrict__ ad3) {
    int n = blockIdx.x;
    int t = threadIdx.x, w = t >> 5, lane = t & 31;
    __shared__ float s_alpha[HEADS][32];
    __shared__ int   s_src[32];
    __shared__ float s_p[HEADS][4];
    __shared__ float s_h3[4];

    int start = g_rowptr[n];
    int cnt   = g_rowptr[n + 1] - start;   // self-loop added implicitly at i==cnt

    float aldn = ald[n * HEADS + w];

    // single-pass online softmax stats (strided over edges)
    float m = -1e30f, z = 0.f;
    for (int i = lane; i <= cnt; i += 32) {
        int s = (i < cnt) ? g_srcs[start + i] : n;
        float e = leaky(als[s * HEADS + w] + aldn);
        float mn = fmaxf(m, e);
        z = z * expf(m - mn) + expf(e - mn);
        m = mn;
    }
#pragma unroll
    for (int off = 16; off; off >>= 1) {
        float mo = __shfl_xor_sync(~0u, m, off);
        float zo = __shfl_xor_sync(~0u, z, off);
        float mn = fmaxf(m, mo);
        z = z * expf(m - mn) + zo * expf(mo - mn);
        m = mn;
    }
    float iz = 1.f / (z + 1e-16f);

    // chunked aggregate: per-warp alpha precompute in smem, broadcast consume
    float4 acc = make_float4(0.f, 0.f, 0.f, 0.f);
    const int cbase = w * HID + lane * 4;
    for (int base = 0; base <= cnt; base += 32) {
        int i = base + lane;
        int s = n;
        float a = 0.f;
        if (i <= cnt) {
            if (i < cnt) s = g_srcs[start + i];
            float e = leaky(als[s * HEADS + w] + aldn);
            a = expf(e - m) * iz;
        }
        s_alpha[w][lane] = a;
        if (w == 0) s_src[lane] = s;
        __syncthreads();
        int lim = min(32, cnt + 1 - base);
        for (int j = 0; j < lim; j++) {
            float alpha = s_alpha[w][j];
            int sj = s_src[j];
            float4 hv = *(const float4*)&h[(size_t)sj * FEAT + cbase];
            acc.x += alpha * hv.x; acc.y += alpha * hv.y;
            acc.z += alpha * hv.z; acc.w += alpha * hv.w;
        }
        __syncthreads();
    }
    float4 b4 = *(const float4*)&bias[cbase];
    acc.x = fmaxf(acc.x + b4.x, 0.f);
    acc.y = fmaxf(acc.y + b4.y, 0.f);
    acc.z = fmaxf(acc.z + b4.z, 0.f);
    acc.w = fmaxf(acc.w + b4.w, 0.f);

    if (fuse3) {
        // project this node's row through W3 [1024,4]; block-reduce
        float p[4];
#pragma unroll
        for (int o = 0; o < 4; o++) {
            p[o] = acc.x * W3[(cbase + 0) * 4 + o]
                 + acc.y * W3[(cbase + 1) * 4 + o]
                 + acc.z * W3[(cbase + 2) * 4 + o]
                 + acc.w * W3[(cbase + 3) * 4 + o];
        }
#pragma unroll
        for (int off = 16; off; off >>= 1) {
#pragma unroll
            for (int o = 0; o < 4; o++) p[o] += __shfl_xor_sync(~0u, p[o], off);
        }
        if (lane == 0) {
#pragma unroll
            for (int o = 0; o < 4; o++) s_p[w][o] = p[o];
        }
        __syncthreads();
        if (t < 4) {
            float v = 0.f;
#pragma unroll
            for (int ww = 0; ww < HEADS; ww++) v += s_p[ww][t];
            g_h3[n * 4 + t] = v;
            s_h3[t] = v;
        }
        __syncthreads();
        if (t == 0) {
            float ss = 0.f, sd = 0.f;
#pragma unroll
            for (int o = 0; o < 4; o++) {
                ss += s_h3[o] * as3[o];
                sd += s_h3[o] * ad3[o];
            }
            g_als3[n] = ss;
            g_ald3[n] = sd;
        }
        return;
    }

    if (round_out) {
        acc.x = __uint_as_float(f2tf32(acc.x));
        acc.y = __uint_as_float(f2tf32(acc.y));
        acc.z = __uint_as_float(f2tf32(acc.z));
        acc.w = __uint_as_float(f2tf32(acc.w));
    }
    *(float4*)&out[(size_t)n * FEAT + cbase] = acc;
}

// ---------------- tf32 mma.sync GEMM + fused alpha2 epilogue ---------------------
// C[M,1024] = A[M,1024] @ W2 (BT[n][k], pre-rounded). Each CTA col-block = 1 head;
// epilogue folds accumulators against a_src2/a_dst2 and atomicAdds into als/ald.
#define LDA  36                       // floats per smem row (32 + 4 pad)
#define TBUF (128 * LDA * 4)          // bytes per tile (18432)
#define BUFB (2 * TBUF)               // A+B per stage (36864)
#define NIT  32                       // 1024 / 32

__device__ __forceinline__ void load_tiles_async(
    const float* __restrict__ A, const float* __restrict__ BT,
    uint32_t sA, uint32_t sB, int row0, int n0, int k0, int M, int tid)
{
#pragma unroll
    for (int j = 0; j < 4; j++) {
        int f = tid + j * 256;            // 0..1023
        int r = f >> 3;                   // 0..127
        int c = f & 7;                    // float4 chunk
        uint32_t so = (uint32_t)(r * LDA + c * 4) * 4;
        bool ok = (row0 + r) < M;
        int ar = ok ? (row0 + r) : 0;
        cp_async16(sA + so, A  + (size_t)ar * FEAT + k0 + c * 4, ok);
        cp_async16(sB + so, BT + (size_t)(n0 + r) * FEAT + k0 + c * 4, true);
    }
}

__global__ __launch_bounds__(256) void tf32_gemm_kernel(
    const float* __restrict__ A, const float* __restrict__ BT,
    float* __restrict__ C, int M,
    const float* __restrict__ asrc2, const float* __restrict__ adst2,
    float* __restrict__ als, float* __restrict__ ald)
{
    extern __shared__ char dsm[];
    const uint32_t sbase = smem_u32(dsm);
    int tid = threadIdx.x;
    int wid = tid >> 5, lane = tid & 31;
    int grp = lane >> 2, tig = lane & 3;
    int wm = (wid & 1) * 64;
    int wn = (wid >> 1) * 32;
    int row0 = blockIdx.y * 128, n0 = blockIdx.x * 128;

    float acc[4][4][4];
#pragma unroll
    for (int i = 0; i < 4; i++)
#pragma unroll
        for (int j = 0; j < 4; j++)
#pragma unroll
            for (int k = 0; k < 4; k++) acc[i][j][k] = 0.f;

    load_tiles_async(A, BT, sbase, sbase + TBUF, row0, n0, 0, M, tid);
    CP_COMMIT();

    for (int it = 0; it < NIT; it++) {
        CP_WAIT0();
        __syncthreads();
        int cb = it & 1;
        if (it + 1 < NIT) {
            uint32_t nb = sbase + (cb ^ 1) * BUFB;
            load_tiles_async(A, BT, nb, nb + TBUF, row0, n0, (it + 1) * 32, M, tid);
            CP_COMMIT();
        }
        const uint32_t* As = (const uint32_t*)(dsm + cb * BUFB);
        const uint32_t* Bs = (const uint32_t*)(dsm + cb * BUFB + TBUF);
#pragma unroll
        for (int ks = 0; ks < 4; ks++) {
            int kk = ks * 8 + tig;
            uint32_t a[4][4];
#pragma unroll
            for (int mt = 0; mt < 4; mt++) {
                int r0 = wm + mt * 16 + grp;
                a[mt][0] = As[r0 * LDA + kk];
                a[mt][1] = As[(r0 + 8) * LDA + kk];
                a[mt][2] = As[r0 * LDA + kk + 4];
                a[mt][3] = As[(r0 + 8) * LDA + kk + 4];
            }
#pragma unroll
            for (int nt = 0; nt < 4; nt++) {
                int rn = wn + nt * 8 + grp;
                uint32_t b0 = Bs[rn * LDA + kk];
                uint32_t b1 = Bs[rn * LDA + kk + 4];
#pragma unroll
                for (int mt = 0; mt < 4; mt++) mma_tf32(acc[mt][nt], a[mt], b0, b1);
            }
        }
        __syncthreads();
    }

    // store epilogue
#pragma unroll
    for (int mt = 0; mt < 4; mt++) {
        int gr = row0 + wm + mt * 16 + grp;
#pragma unroll
        for (int nt = 0; nt < 4; nt++) {
            int gc = n0 + wn + nt * 8 + 2 * tig;
            if (gr < M) {
                float2 v0 = make_float2(acc[mt][nt][0], acc[mt][nt][1]);
                *(float2*)&C[(size_t)gr * FEAT + gc] = v0;
            }
            if (gr + 8 < M) {
                float2 v1 = make_float2(acc[mt][nt][2], acc[mt][nt][3]);
                *(float2*)&C[(size_t)(gr + 8) * FEAT + gc] = v1;
            }
        }
    }

    // fused alpha2 epilogue: this CTA's 128-col block = head blockIdx.x
    {
        int head = blockIdx.x;
        float asv[8], adv[8];
#pragma unroll
        for (int nt = 0; nt < 4; nt++) {
            int c0 = head * 128 + wn + nt * 8 + 2 * tig;
            asv[nt * 2]     = asrc2[c0];
            asv[nt * 2 + 1] = asrc2[c0 + 1];
            adv[nt * 2]     = adst2[c0];
            adv[nt * 2 + 1] = adst2[c0 + 1];
        }
#pragma unroll
        for (int mt = 0; mt < 4; mt++) {
            float s0 = 0.f, s1 = 0.f, d0 = 0.f, d1 = 0.f;
#pragma unroll
            for (int nt = 0; nt < 4; nt++) {
                s0 += acc[mt][nt][0] * asv[nt * 2] + acc[mt][nt][1] * asv[nt * 2 + 1];
                s1 += acc[mt][nt][2] * asv[nt * 2] + acc[mt][nt][3] * asv[nt * 2 + 1];
                d0 += acc[mt][nt][0] * adv[nt * 2] + acc[mt][nt][1] * adv[nt * 2 + 1];
                d1 += acc[mt][nt][2] * adv[nt * 2] + acc[mt][nt][3] * adv[nt * 2 + 1];
            }
            // reduce over the 4 lanes (tig) sharing the same rows
            s0 += __shfl_xor_sync(~0u, s0, 1); s0 += __shfl_xor_sync(~0u, s0, 2);
            s1 += __shfl_xor_sync(~0u, s1, 1); s1 += __shfl_xor_sync(~0u, s1, 2);
            d0 += __shfl_xor_sync(~0u, d0, 1); d0 += __shfl_xor_sync(~0u, d0, 2);
            d1 += __shfl_xor_sync(~0u, d1, 1); d1 += __shfl_xor_sync(~0u, d1, 2);
            if (tig == 0) {
                int gr = row0 + wm + mt * 16 + grp;
                if (gr < M) {
                    atomicAdd(&als[gr * HEADS + head], s0);
                    atomicAdd(&ald[gr * HEADS + head], d0);
                }
                if (gr + 8 < M) {
                    atomicAdd(&als[(gr + 8) * HEADS + head], s1);
                    atomicAdd(&ald[(gr + 8) * HEADS + head], d1);
                }
            }
        }
    }
}

// ---------------- layer-3 aggregation (warp per node, 1 head, C=4) --------------
__global__ __launch_bounds__(256) void agg3_kernel(const float* __restrict__ b3,
                                                   float* __restrict__ out) {
    int n = (blockIdx.x * blockDim.x + threadIdx.x) >> 5;
    int lane = threadIdx.x & 31;
    if (n >= N_NODES) return;
    int start = g_rowptr[n];
    int cnt   = g_rowptr[n + 1] - start;
    float aldn = g_ald3[n];
    float mx = -1e30f;
    for (int i = lane; i <= cnt; i += 32) {
        int s = (i < cnt) ? g_srcs[start + i] : n;
        mx = fmaxf(mx, leaky(g_als3[s] + aldn));
    }
#pragma unroll
    for (int off = 16; off; off >>= 1) mx = fmaxf(mx, __shfl_xor_sync(~0u, mx, off));
    float z = 0.f;
    float c0 = 0.f, c1 = 0.f, c2 = 0.f, c3 = 0.f;
    for (int i = lane; i <= cnt; i += 32) {
        int s = (i < cnt) ? g_srcs[start + i] : n;
        float e = leaky(g_als3[s] + aldn);
        float ex = expf(e - mx);
        z += ex;
        c0 += ex * g_h3[s * 4 + 0];
        c1 += ex * g_h3[s * 4 + 1];
        c2 += ex * g_h3[s * 4 + 2];
        c3 += ex * g_h3[s * 4 + 3];
    }
#pragma unroll
    for (int off = 16; off; off >>= 1) {
        z  += __shfl_xor_sync(~0u, z, off);
        c0 += __shfl_xor_sync(~0u, c0, off);
        c1 += __shfl_xor_sync(~0u, c1, off);
        c2 += __shfl_xor_sync(~0u, c2, off);
        c3 += __shfl_xor_sync(~0u, c3, off);
    }
    float iz = 1.f / (z + 1e-16f);
    if (lane == 0) {
        out[n * 4 + 0] = fmaxf(c0 * iz + b3[0], 0.f);
        out[n * 4 + 1] = fmaxf(c1 * iz + b3[1], 0.f);
        out[n * 4 + 2] = fmaxf(c2 * iz + b3[2], 0.f);
        out[n * 4 + 3] = fmaxf(c3 * iz + b3[3], 0.f);
    }
}

// ---------------- launch ----------------
extern "C" void kernel_launch(void* const* d_in, const int* in_sizes, int n_in,
                              void* d_out, int out_size) {
    const float* x      = (const float*)d_in[0];
    const void*  eidx   = d_in[1];
    const float* W1     = (const float*)d_in[2];
    const float* a_src1 = (const float*)d_in[3];
    const float* a_dst1 = (const float*)d_in[4];
    const float* b1     = (const float*)d_in[5];
    const float* W2     = (const float*)d_in[6];
    const float* a_src2 = (const float*)d_in[7];
    const float* a_dst2 = (const float*)d_in[8];
    const float* b2     = (const float*)d_in[9];
    const float* W3     = (const float*)d_in[10];
    const float* a_src3 = (const float*)d_in[11];
    const float* a_dst3 = (const float*)d_in[12];
    const float* b3     = (const float*)d_in[13];
    float* out = (float*)d_out;

    float* bufA; cudaGetSymbolAddress((void**)&bufA, g_bufA);
    float* bufB; cudaGetSymbolAddress((void**)&bufB, g_bufB);
    float* w2t;  cudaGetSymbolAddress((void**)&w2t,  g_W2T);
    float* als;  cudaGetSymbolAddress((void**)&als,  g_als);
    float* ald;  cudaGetSymbolAddress((void**)&ald,  g_ald);

    const int g1_smem = G1N * FEAT * sizeof(float);   // 64 KB
    static bool attr_set = false;
    if (!attr_set) {
        cudaFuncSetAttribute(tf32_gemm_kernel,
                             cudaFuncAttributeMaxDynamicSharedMemorySize, 2 * BUFB);
        cudaFuncSetAttribute(gemm1_kernel,
                             cudaFuncAttributeMaxDynamicSharedMemorySize, g1_smem);
        attr_set = true;
    }

    // CSR build (detect fused into zero)
    zero_kernel<<<(N_NODES + 255) / 256, 256>>>((const int*)eidx);
    count_kernel<<<(E_EDGES + 255) / 256, 256>>>(eidx);
    scan_kernel<<<1, 1024>>>();
    scatter_kernel<<<(E_EDGES + 255) / 256, 256>>>(eidx);

    // layer 1 (GEMM + fused logits)
    gemm1_kernel<<<N_NODES / G1N, 256, g1_smem>>>(x, W1, a_src1, a_dst1, bufA, als, ald);
    agg_kernel<<<N_NODES, 256>>>(bufA, als, ald, b1, bufB, 1, 0, nullptr, nullptr, nullptr);

    // layer 2 (tf32 mma.sync GEMM + fused alpha2 epilogue)
    transpose_kernel<<<dim3(32, 32), dim3(32, 8)>>>(W2, w2t);
    zero_als_kernel<<<(N_NODES * HEADS + 255) / 256, 256>>>(als, ald);
    dim3 g2(FEAT / 128, (N_NODES + 127) / 128);
    tf32_gemm_kernel<<<g2, 256, 2 * BUFB>>>(bufB, w2t, bufA, N_NODES,
                                            a_src2, a_dst2, als, ald);
    // layer 2 aggregate with fused layer-3 projection (emits h3/als3/ald3)
    agg_kernel<<<N_NODES, 256>>>(bufA, als, ald, b2, bufB, 0, 1, W3, a_src3, a_dst3);

    // layer 3 aggregation
    agg3_kernel<<<(N_NODES * 32 + 255) / 256, 256>>>(b3, out);
}

// round 12
// speedup vs baseline: 1.1053x; 1.1053x over previous
#include <cuda_runtime.h>
#include <cuda_bf16.h>
#include <cstdint>

#define N_NODES 10000
#define E_EDGES 160000
#define IN_CH   14
#define HID     128
#define HEADS   8
#define OUT_CH  4
#define FEAT    (HEADS*HID)   // 1024

// ---------------- scratch (static device memory; no allocations) ----------------
__device__ float g_bufA[(size_t)N_NODES * FEAT];
__device__ float g_bufB[(size_t)N_NODES * FEAT];
__device__ float g_W2T[(size_t)FEAT * FEAT];
__device__ float g_als[N_NODES * HEADS];
__device__ float g_ald[N_NODES * HEADS];
__device__ float g_h3[N_NODES * OUT_CH];
__device__ float g_als3[N_NODES];
__device__ float g_ald3[N_NODES];
__device__ int   g_deg[N_NODES];
__device__ int   g_cursor[N_NODES];
__device__ int   g_rowptr[N_NODES + 1];
__device__ int   g_srcs[E_EDGES];
__device__ int   g_is64;

// ---------------- small PTX helpers ----------------
__device__ __forceinline__ uint32_t smem_u32(const void* p) {
    uint32_t a;
    asm("{ .reg .u64 t; cvta.to.shared.u64 t, %1; cvt.u32.u64 %0, t; }" : "=r"(a) : "l"(p));
    return a;
}

__device__ __forceinline__ void cp_async16(uint32_t s, const void* g, bool pred) {
    int sz = pred ? 16 : 0;
    asm volatile("cp.async.cg.shared.global [%0], [%1], 16, %2;\n"
                 :: "r"(s), "l"(g), "r"(sz) : "memory");
}
#define CP_COMMIT()  asm volatile("cp.async.commit_group;" ::: "memory")
#define CP_WAIT0()   asm volatile("cp.async.wait_group 0;" ::: "memory")

__device__ __forceinline__ uint32_t f2tf32(float f) {
    uint32_t r;
    asm("cvt.rna.tf32.f32 %0, %1;" : "=r"(r) : "f"(f));
    return r;
}

__device__ __forceinline__ void mma_tf32(float* c, const uint32_t* a, uint32_t b0, uint32_t b1) {
    asm volatile(
        "mma.sync.aligned.m16n8k8.row.col.f32.tf32.tf32.f32 "
        "{%0,%1,%2,%3}, {%4,%5,%6,%7}, {%8,%9}, {%0,%1,%2,%3};"
        : "+f"(c[0]), "+f"(c[1]), "+f"(c[2]), "+f"(c[3])
        : "r"(a[0]), "r"(a[1]), "r"(a[2]), "r"(a[3]), "r"(b0), "r"(b1));
}

__device__ __forceinline__ float leaky(float e) {
    return e > 0.f ? e : 0.2f * e;
}

// ---------------- edge index access (int32 vs int64 detected at runtime) --------
__device__ __forceinline__ int edge_val(const void* idx, int is64, long i) {
    if (is64) return (int)((const long long*)idx)[i];
    return ((const int*)idx)[i];
}

// ---------------- CSR build ----------------
// zero + edge-width detection fused
__global__ void zero_kernel(const int* p) {
    int i = blockIdx.x * blockDim.x + threadIdx.x;
    if (i < N_NODES) { g_deg[i] = 0; g_cursor[i] = 0; }
    if (blockIdx.x == 0 && threadIdx.x == 0) {
        int is64 = 1;
        for (int k = 0; k < 64; k++) {
            if (p[2*k + 1] != 0) { is64 = 0; break; }
        }
        g_is64 = is64;
    }
}

__global__ void count_kernel(const void* idx) {
    int e = blockIdx.x * blockDim.x + threadIdx.x;
    if (e < E_EDGES) {
        int f = g_is64;
        int d = edge_val(idx, f, (long)E_EDGES + e);
        atomicAdd(&g_deg[d], 1);
    }
}

// shuffle-based scan: 1024 threads, 10 elems/thread, 2 barriers
__global__ void scan_kernel() {
    __shared__ int wsum[32];
    int t = threadIdx.x, lane = t & 31, w = t >> 5;
    const int CH = (N_NODES + 1023) / 1024;  // 10
    int base = t * CH;
    int s = 0;
#pragma unroll
    for (int i = 0; i < CH; i++) {
        int idx = base + i;
        if (idx < N_NODES) s += g_deg[idx];
    }
    int v = s;
#pragma unroll
    for (int off = 1; off < 32; off <<= 1) {
        int u = __shfl_up_sync(~0u, v, off);
        if (lane >= off) v += u;
    }
    if (lane == 31) wsum[w] = v;
    __syncthreads();
    if (w == 0) {
        int x = wsum[lane];
#pragma unroll
        for (int off = 1; off < 32; off <<= 1) {
            int u = __shfl_up_sync(~0u, x, off);
            if (lane >= off) x += u;
        }
        wsum[lane] = x;
    }
    __syncthreads();
    int excl = v - s + (w > 0 ? wsum[w - 1] : 0);
    int run = excl;
#pragma unroll
    for (int i = 0; i < CH; i++) {
        int idx = base + i;
        if (idx < N_NODES) { g_rowptr[idx] = run; run += g_deg[idx]; }
    }
    if (t == 1023) g_rowptr[N_NODES] = run;
}

__global__ void scatter_kernel(const void* idx) {
    int e = blockIdx.x * blockDim.x + threadIdx.x;
    if (e < E_EDGES) {
        int f = g_is64;
        int s = edge_val(idx, f, e);
        int d = edge_val(idx, f, (long)E_EDGES + e);
        int pos = g_rowptr[d] + atomicAdd(&g_cursor[d], 1);
        g_srcs[pos] = s;
    }
}

// ---------------- Layer-1 GEMM: [N,14] @ [14,1024], 16 nodes per block -----------
#define G1N 16
__global__ __launch_bounds__(256) void gemm1_kernel(const float* __restrict__ x,
                                                    const float* __restrict__ W1,
                                                    float* __restrict__ h) {
    __shared__ float xs[G1N * IN_CH];
    int nb = blockIdx.x * G1N;
    int t = threadIdx.x;
    if (t < G1N * IN_CH) xs[t] = x[nb * IN_CH + t];
    __syncthreads();
#pragma unroll
    for (int j = 0; j < 4; j++) {
        int c = t + j * 256;
        float w[IN_CH];
#pragma unroll
        for (int k = 0; k < IN_CH; k++) w[k] = W1[k * FEAT + c];
        for (int n = 0; n < G1N; n++) {
            float acc = 0.f;
#pragma unroll
            for (int k = 0; k < IN_CH; k++) acc += xs[n * IN_CH + k] * w[k];
            h[(size_t)(nb + n) * FEAT + c] = acc;
        }
    }
}

// ---------------- W2 transpose + tf32 pre-round: W2T[n][k] = rna(W2[k][n]) -------
__global__ __launch_bounds__(256) void transpose_kernel(const float* __restrict__ W,
                                                        float* __restrict__ WT) {
    __shared__ float t[32][33];
    int bx = blockIdx.x * 32, by = blockIdx.y * 32;
    int x = bx + threadIdx.x;
    int y = by + threadIdx.y;
#pragma unroll
    for (int j = 0; j < 32; j += 8) t[threadIdx.y + j][threadIdx.x] = W[(size_t)(y + j) * FEAT + x];
    __syncthreads();
    int x2 = by + threadIdx.x;
    int y2 = bx + threadIdx.y;
#pragma unroll
    for (int j = 0; j < 32; j += 8)
        WT[(size_t)(y2 + j) * FEAT + x2] = __uint_as_float(f2tf32(t[threadIdx.x][threadIdx.y + j]));
}

// ---------------- attention logits: als/ald [N,8] ----------------
__global__ __launch_bounds__(256) void alpha_kernel(const float* __restrict__ h,
                                                    const float* __restrict__ asrc,
                                                    const float* __restrict__ adst,
                                                    float* __restrict__ als,
                                                    float* __restrict__ ald) {
    int n = blockIdx.x;
    int t = threadIdx.x, w = t >> 5, lane = t & 31;
    const float* hr = h + (size_t)n * FEAT + w * HID;
    float ss = 0.f, sd = 0.f;
#pragma unroll
    for (int c = lane; c < HID; c += 32) {
        float v = hr[c];
        ss += v * asrc[w * HID + c];
        sd += v * adst[w * HID + c];
    }
#pragma unroll
    for (int off = 16; off; off >>= 1) {
        ss += __shfl_xor_sync(~0u, ss, off);
        sd += __shfl_xor_sync(~0u, sd, off);
    }
    if (lane == 0) { als[n * HEADS + w] = ss; ald[n * HEADS + w] = sd; }
}

// ---------------- fused per-node softmax + aggregate (heads=8, C=128) -----------
// ROUND: store tf32-rounded output (bit-identical to in-GEMM rounding)
// FUSE3: project through W3 and emit h3/als3/ald3 instead of writing out
template <int ROUND, int FUSE3>
__global__ __launch_bounds__(256) void agg_kernel(const float* __restrict__ h,
                                                  const float* __restrict__ als,
                                                  const float* __restrict__ ald,
                                                  const float* __restrict__ bias,
                                                  float* __restrict__ out,
                                                  const float* __restrict__ W3,
                                                  const float* __restrict__ as3,
                                                  const float* __restrict__ ad3) {
    int n = blockIdx.x;
    int t = threadIdx.x, w = t >> 5, lane = t & 31;
    __shared__ float s_alpha[HEADS][32];
    __shared__ int   s_src[32];
    __shared__ float s_p[HEADS][4];
    __shared__ float s_h3[4];

    int start = g_rowptr[n];
    int cnt   = g_rowptr[n + 1] - start;   // self-loop added implicitly at i==cnt

    float aldn = ald[n * HEADS + w];

    // single-pass online softmax stats (strided over edges)
    float m = -1e30f, z = 0.f;
    for (int i = lane; i <= cnt; i += 32) {
        int s = (i < cnt) ? g_srcs[start + i] : n;
        float e = leaky(als[s * HEADS + w] + aldn);
        float mn = fmaxf(m, e);
        z = z * expf(m - mn) + expf(e - mn);
        m = mn;
    }
#pragma unroll
    for (int off = 16; off; off >>= 1) {
        float mo = __shfl_xor_sync(~0u, m, off);
        float zo = __shfl_xor_sync(~0u, z, off);
        float mn = fmaxf(m, mo);
        z = z * expf(m - mn) + zo * expf(mo - mn);
        m = mn;
    }
    float iz = 1.f / (z + 1e-16f);

    // chunked aggregate: per-warp alpha precompute in smem, broadcast consume
    float4 acc = make_float4(0.f, 0.f, 0.f, 0.f);
    const int cbase = w * HID + lane * 4;
    for (int base = 0; base <= cnt; base += 32) {
        int i = base + lane;
        int s = n;
        float a = 0.f;
        if (i <= cnt) {
            if (i < cnt) s = g_srcs[start + i];
            float e = leaky(als[s * HEADS + w] + aldn);
            a = expf(e - m) * iz;
        }
        s_alpha[w][lane] = a;
        if (w == 0) s_src[lane] = s;
        __syncthreads();
        int lim = min(32, cnt + 1 - base);
        for (int j = 0; j < lim; j++) {
            float alpha = s_alpha[w][j];
            int sj = s_src[j];
            float4 hv = *(const float4*)&h[(size_t)sj * FEAT + cbase];
            acc.x += alpha * hv.x; acc.y += alpha * hv.y;
            acc.z += alpha * hv.z; acc.w += alpha * hv.w;
        }
        __syncthreads();
    }
    float4 b4 = *(const float4*)&bias[cbase];
    acc.x = fmaxf(acc.x + b4.x, 0.f);
    acc.y = fmaxf(acc.y + b4.y, 0.f);
    acc.z = fmaxf(acc.z + b4.z, 0.f);
    acc.w = fmaxf(acc.w + b4.w, 0.f);

    if (FUSE3) {
        // project this node's row through W3 [1024,4]; block-reduce
        float p0, p1, p2, p3;
        {
            float4 w0 = *(const float4*)&W3[(cbase + 0) * 4];
            float4 w1 = *(const float4*)&W3[(cbase + 1) * 4];
            float4 w2 = *(const float4*)&W3[(cbase + 2) * 4];
            float4 w3v = *(const float4*)&W3[(cbase + 3) * 4];
            p0 = acc.x * w0.x + acc.y * w1.x + acc.z * w2.x + acc.w * w3v.x;
            p1 = acc.x * w0.y + acc.y * w1.y + acc.z * w2.y + acc.w * w3v.y;
            p2 = acc.x * w0.z + acc.y * w1.z + acc.z * w2.z + acc.w * w3v.z;
            p3 = acc.x * w0.w + acc.y * w1.w + acc.z * w2.w + acc.w * w3v.w;
        }
#pragma unroll
        for (int off = 16; off; off >>= 1) {
            p0 += __shfl_xor_sync(~0u, p0, off);
            p1 += __shfl_xor_sync(~0u, p1, off);
            p2 += __shfl_xor_sync(~0u, p2, off);
            p3 += __shfl_xor_sync(~0u, p3, off);
        }
        if (lane == 0) {
            s_p[w][0] = p0; s_p[w][1] = p1; s_p[w][2] = p2; s_p[w][3] = p3;
        }
        __syncthreads();
        if (t < 4) {
            float v = 0.f;
#pragma unroll
            for (int ww = 0; ww < HEADS; ww++) v += s_p[ww][t];
            g_h3[n * 4 + t] = v;
            s_h3[t] = v;
        }
        __syncthreads();
        if (t == 0) {
            float ss = 0.f, sd = 0.f;
#pragma unroll
            for (int o = 0; o < 4; o++) {
                ss += s_h3[o] * as3[o];
                sd += s_h3[o] * ad3[o];
            }
            g_als3[n] = ss;
            g_ald3[n] = sd;
        }
        return;
    }

    if (ROUND) {
        acc.x = __uint_as_float(f2tf32(acc.x));
        acc.y = __uint_as_float(f2tf32(acc.y));
        acc.z = __uint_as_float(f2tf32(acc.z));
        acc.w = __uint_as_float(f2tf32(acc.w));
    }
    *(float4*)&out[(size_t)n * FEAT + cbase] = acc;
}

// ---------------- tf32 mma.sync GEMM: C[M,1024] = A[M,1024] @ W2, BT[n][k] -------
// Inputs pre-rounded to tf32; mainloop is raw LDS + HMMA only.
#define LDA  36                       // floats per smem row (32 + 4 pad)
#define TBUF (128 * LDA * 4)          // bytes per tile (18432)
#define BUFB (2 * TBUF)               // A+B per stage (36864)
#define NIT  32                       // 1024 / 32

__device__ __forceinline__ void load_tiles_async(
    const float* __restrict__ A, const float* __restrict__ BT,
    uint32_t sA, uint32_t sB, int row0, int n0, int k0, int M, int tid)
{
#pragma unroll
    for (int j = 0; j < 4; j++) {
        int f = tid + j * 256;            // 0..1023
        int r = f >> 3;                   // 0..127
        int c = f & 7;                    // float4 chunk
        uint32_t so = (uint32_t)(r * LDA + c * 4) * 4;
        bool ok = (row0 + r) < M;
        int ar = ok ? (row0 + r) : 0;
        cp_async16(sA + so, A  + (size_t)ar * FEAT + k0 + c * 4, ok);
        cp_async16(sB + so, BT + (size_t)(n0 + r) * FEAT + k0 + c * 4, true);
    }
}

__global__ __launch_bounds__(256) void tf32_gemm_kernel(
    const float* __restrict__ A, const float* __restrict__ BT,
    float* __restrict__ C, int M)
{
    extern __shared__ char dsm[];
    const uint32_t sbase = smem_u32(dsm);
    int tid = threadIdx.x;
    int wid = tid >> 5, lane = tid & 31;
    int grp = lane >> 2, tig = lane & 3;
    int wm = (wid & 1) * 64;
    int wn = (wid >> 1) * 32;
    int row0 = blockIdx.y * 128, n0 = blockIdx.x * 128;

    float acc[4][4][4];
#pragma unroll
    for (int i = 0; i < 4; i++)
#pragma unroll
        for (int j = 0; j < 4; j++)
#pragma unroll
            for (int k = 0; k < 4; k++) acc[i][j][k] = 0.f;

    load_tiles_async(A, BT, sbase, sbase + TBUF, row0, n0, 0, M, tid);
    CP_COMMIT();

    for (int it = 0; it < NIT; it++) {
        CP_WAIT0();
        __syncthreads();
        int cb = it & 1;
        if (it + 1 < NIT) {
            uint32_t nb = sbase + (cb ^ 1) * BUFB;
            load_tiles_async(A, BT, nb, nb + TBUF, row0, n0, (it + 1) * 32, M, tid);
            CP_COMMIT();
        }
        const uint32_t* As = (const uint32_t*)(dsm + cb * BUFB);
        const uint32_t* Bs = (const uint32_t*)(dsm + cb * BUFB + TBUF);
#pragma unroll
        for (int ks = 0; ks < 4; ks++) {
            int kk = ks * 8 + tig;
            uint32_t a[4][4];
#pragma unroll
            for (int mt = 0; mt < 4; mt++) {
                int r0 = wm + mt * 16 + grp;
                a[mt][0] = As[r0 * LDA + kk];
                a[mt][1] = As[(r0 + 8) * LDA + kk];
                a[mt][2] = As[r0 * LDA + kk + 4];
                a[mt][3] = As[(r0 + 8) * LDA + kk + 4];
            }
#pragma unroll
            for (int nt = 0; nt < 4; nt++) {
                int rn = wn + nt * 8 + grp;
                uint32_t b0 = Bs[rn * LDA + kk];
                uint32_t b1 = Bs[rn * LDA + kk + 4];
#pragma unroll
                for (int mt = 0; mt < 4; mt++) mma_tf32(acc[mt][nt], a[mt], b0, b1);
            }
        }
        __syncthreads();
    }

    // epilogue
#pragma unroll
    for (int mt = 0; mt < 4; mt++) {
        int gr = row0 + wm + mt * 16 + grp;
#pragma unroll
        for (int nt = 0; nt < 4; nt++) {
            int gc = n0 + wn + nt * 8 + 2 * tig;
            if (gr < M) {
                float2 v0 = make_float2(acc[mt][nt][0], acc[mt][nt][1]);
                *(float2*)&C[(size_t)gr * FEAT + gc] = v0;
            }
            if (gr + 8 < M) {
                float2 v1 = make_float2(acc[mt][nt][2], acc[mt][nt][3]);
                *(float2*)&C[(size_t)(gr + 8) * FEAT + gc] = v1;
            }
        }
    }
}

// ---------------- layer-3 aggregation (warp per node, 1 head, C=4) --------------
__global__ __launch_bounds__(256) void agg3_kernel(const float* __restrict__ b3,
                                                   float* __restrict__ out) {
    int n = (blockIdx.x * blockDim.x + threadIdx.x) >> 5;
    int lane = threadIdx.x & 31;
    if (n >= N_NODES) return;
    int start = g_rowptr[n];
    int cnt   = g_rowptr[n + 1] - start;
    float aldn = g_ald3[n];
    float mx = -1e30f;
    for (int i = lane; i <= cnt; i += 32) {
        int s = (i < cnt) ? g_srcs[start + i] : n;
        mx = fmaxf(mx, leaky(g_als3[s] + aldn));
    }
#pragma unroll
    for (int off = 16; off; off >>= 1) mx = fmaxf(mx, __shfl_xor_sync(~0u, mx, off));
    float z = 0.f;
    float c0 = 0.f, c1 = 0.f, c2 = 0.f, c3 = 0.f;
    for (int i = lane; i <= cnt; i += 32) {
        int s = (i < cnt) ? g_srcs[start + i] : n;
        float e = leaky(g_als3[s] + aldn);
        float ex = expf(e - mx);
        z += ex;
        c0 += ex * g_h3[s * 4 + 0];
        c1 += ex * g_h3[s * 4 + 1];
        c2 += ex * g_h3[s * 4 + 2];
        c3 += ex * g_h3[s * 4 + 3];
    }
#pragma unroll
    for (int off = 16; off; off >>= 1) {
        z  += __shfl_xor_sync(~0u, z, off);
        c0 += __shfl_xor_sync(~0u, c0, off);
        c1 += __shfl_xor_sync(~0u, c1, off);
        c2 += __shfl_xor_sync(~0u, c2, off);
        c3 += __shfl_xor_sync(~0u, c3, off);
    }
    float iz = 1.f / (z + 1e-16f);
    if (lane == 0) {
        out[n * 4 + 0] = fmaxf(c0 * iz + b3[0], 0.f);
        out[n * 4 + 1] = fmaxf(c1 * iz + b3[1], 0.f);
        out[n * 4 + 2] = fmaxf(c2 * iz + b3[2], 0.f);
        out[n * 4 + 3] = fmaxf(c3 * iz + b3[3], 0.f);
    }
}

// ---------------- launch ----------------
extern "C" void kernel_launch(void* const* d_in, const int* in_sizes, int n_in,
                              void* d_out, int out_size) {
    const float* x      = (const float*)d_in[0];
    const void*  eidx   = d_in[1];
    const float* W1     = (const float*)d_in[2];
    const float* a_src1 = (const float*)d_in[3];
    const float* a_dst1 = (const float*)d_in[4];
    const float* b1     = (const float*)d_in[5];
    const float* W2     = (const float*)d_in[6];
    const float* a_src2 = (const float*)d_in[7];
    const float* a_dst2 = (const float*)d_in[8];
    const float* b2     = (const float*)d_in[9];
    const float* W3     = (const float*)d_in[10];
    const float* a_src3 = (const float*)d_in[11];
    const float* a_dst3 = (const float*)d_in[12];
    const float* b3     = (const float*)d_in[13];
    float* out = (float*)d_out;

    float* bufA; cudaGetSymbolAddress((void**)&bufA, g_bufA);
    float* bufB; cudaGetSymbolAddress((void**)&bufB, g_bufB);
    float* w2t;  cudaGetSymbolAddress((void**)&w2t,  g_W2T);
    float* als;  cudaGetSymbolAddress((void**)&als,  g_als);
    float* ald;  cudaGetSymbolAddress((void**)&ald,  g_ald);

    static bool attr_set = false;
    if (!attr_set) {
        cudaFuncSetAttribute(tf32_gemm_kernel,
                             cudaFuncAttributeMaxDynamicSharedMemorySize, 2 * BUFB);
        attr_set = true;
    }

    // CSR build (detect fused into zero)
    zero_kernel<<<(N_NODES + 255) / 256, 256>>>((const int*)eidx);
    count_kernel<<<(E_EDGES + 255) / 256, 256>>>(eidx);
    scan_kernel<<<1, 1024>>>();
    scatter_kernel<<<(E_EDGES + 255) / 256, 256>>>(eidx);

    // layer 1
    gemm1_kernel<<<N_NODES / G1N, 256>>>(x, W1, bufA);
    alpha_kernel<<<N_NODES, 256>>>(bufA, a_src1, a_dst1, als, ald);
    agg_kernel<1, 0><<<N_NODES, 256>>>(bufA, als, ald, b1, bufB,
                                       nullptr, nullptr, nullptr);

    // layer 2 (tf32 mma.sync GEMM, pre-rounded inputs)
    transpose_kernel<<<dim3(32, 32), dim3(32, 8)>>>(W2, w2t);
    dim3 g2(FEAT / 128, (N_NODES + 127) / 128);
    tf32_gemm_kernel<<<g2, 256, 2 * BUFB>>>(bufB, w2t, bufA, N_NODES);
    alpha_kernel<<<N_NODES, 256>>>(bufA, a_src2, a_dst2, als, ald);
    // layer-2 aggregate with fused layer-3 projection (no bufB write, no gemm3)
    agg_kernel<0, 1><<<N_NODES, 256>>>(bufA, als, ald, b2, nullptr,
                                       W3, a_src3, a_dst3);

    // layer 3 aggregation
    agg3_kernel<<<(N_NODES * 32 + 255) / 256, 256>>>(b3, out);
}

// round 14
// speedup vs baseline: 1.1105x; 1.0047x over previous
#include <cuda_runtime.h>
#include <cuda_bf16.h>
#include <cuda_fp16.h>
#include <cstdint>

#define N_NODES 10000
#define E_EDGES 160000
#define IN_CH   14
#define HID     128
#define HEADS   8
#define OUT_CH  4
#define FEAT    (HEADS*HID)   // 1024

// ---------------- scratch (static device memory; no allocations) ----------------
__device__ float  g_bufA[(size_t)N_NODES * FEAT];
__device__ float  g_bufB[(size_t)N_NODES * FEAT];
__device__ __half g_h16[(size_t)N_NODES * FEAT];   // fp16 copy of h for agg gather
__device__ float  g_W2T[(size_t)FEAT * FEAT];
__device__ float  g_als[N_NODES * HEADS];
__device__ float  g_ald[N_NODES * HEADS];
__device__ float  g_h3[N_NODES * OUT_CH];
__device__ float  g_als3[N_NODES];
__device__ float  g_ald3[N_NODES];
__device__ int    g_deg[N_NODES];
__device__ int    g_cursor[N_NODES];
__device__ int    g_rowptr[N_NODES + 1];
__device__ int    g_srcs[E_EDGES];
__device__ int    g_is64;

// ---------------- small PTX helpers ----------------
__device__ __forceinline__ uint32_t smem_u32(const void* p) {
    uint32_t a;
    asm("{ .reg .u64 t; cvta.to.shared.u64 t, %1; cvt.u32.u64 %0, t; }" : "=r"(a) : "l"(p));
    return a;
}

__device__ __forceinline__ void cp_async16(uint32_t s, const void* g, bool pred) {
    int sz = pred ? 16 : 0;
    asm volatile("cp.async.cg.shared.global [%0], [%1], 16, %2;\n"
                 :: "r"(s), "l"(g), "r"(sz) : "memory");
}
#define CP_COMMIT()  asm volatile("cp.async.commit_group;" ::: "memory")
#define CP_WAIT0()   asm volatile("cp.async.wait_group 0;" ::: "memory")

__device__ __forceinline__ uint32_t f2tf32(float f) {
    uint32_t r;
    asm("cvt.rna.tf32.f32 %0, %1;" : "=r"(r) : "f"(f));
    return r;
}

__device__ __forceinline__ void mma_tf32(float* c, const uint32_t* a, uint32_t b0, uint32_t b1) {
    asm volatile(
        "mma.sync.aligned.m16n8k8.row.col.f32.tf32.tf32.f32 "
        "{%0,%1,%2,%3}, {%4,%5,%6,%7}, {%8,%9}, {%0,%1,%2,%3};"
        : "+f"(c[0]), "+f"(c[1]), "+f"(c[2]), "+f"(c[3])
        : "r"(a[0]), "r"(a[1]), "r"(a[2]), "r"(a[3]), "r"(b0), "r"(b1));
}

__device__ __forceinline__ float leaky(float e) {
    return e > 0.f ? e : 0.2f * e;
}

// ---------------- edge index access (int32 vs int64 detected at runtime) --------
__device__ __forceinline__ int edge_val(const void* idx, int is64, long i) {
    if (is64) return (int)((const long long*)idx)[i];
    return ((const int*)idx)[i];
}

// ---------------- CSR build ----------------
// zero + edge-width detection fused
__global__ void zero_kernel(const int* p) {
    int i = blockIdx.x * blockDim.x + threadIdx.x;
    if (i < N_NODES) { g_deg[i] = 0; g_cursor[i] = 0; }
    if (blockIdx.x == 0 && threadIdx.x == 0) {
        int is64 = 1;
        for (int k = 0; k < 64; k++) {
            if (p[2*k + 1] != 0) { is64 = 0; break; }
        }
        g_is64 = is64;
    }
}

__global__ void count_kernel(const void* idx) {
    int e = blockIdx.x * blockDim.x + threadIdx.x;
    if (e < E_EDGES) {
        int f = g_is64;
        int d = edge_val(idx, f, (long)E_EDGES + e);
        atomicAdd(&g_deg[d], 1);
    }
}

// shuffle-based scan: 1024 threads, 10 elems/thread, 2 barriers
__global__ void scan_kernel() {
    __shared__ int wsum[32];
    int t = threadIdx.x, lane = t & 31, w = t >> 5;
    const int CH = (N_NODES + 1023) / 1024;  // 10
    int base = t * CH;
    int s = 0;
#pragma unroll
    for (int i = 0; i < CH; i++) {
        int idx = base + i;
        if (idx < N_NODES) s += g_deg[idx];
    }
    int v = s;
#pragma unroll
    for (int off = 1; off < 32; off <<= 1) {
        int u = __shfl_up_sync(~0u, v, off);
        if (lane >= off) v += u;
    }
    if (lane == 31) wsum[w] = v;
    __syncthreads();
    if (w == 0) {
        int x = wsum[lane];
#pragma unroll
        for (int off = 1; off < 32; off <<= 1) {
            int u = __shfl_up_sync(~0u, x, off);
            if (lane >= off) x += u;
        }
        wsum[lane] = x;
    }
    __syncthreads();
    int excl = v - s + (w > 0 ? wsum[w - 1] : 0);
    int run = excl;
#pragma unroll
    for (int i = 0; i < CH; i++) {
        int idx = base + i;
        if (idx < N_NODES) { g_rowptr[idx] = run; run += g_deg[idx]; }
    }
    if (t == 1023) g_rowptr[N_NODES] = run;
}

__global__ void scatter_kernel(const void* idx) {
    int e = blockIdx.x * blockDim.x + threadIdx.x;
    if (e < E_EDGES) {
        int f = g_is64;
        int s = edge_val(idx, f, e);
        int d = edge_val(idx, f, (long)E_EDGES + e);
        int pos = g_rowptr[d] + atomicAdd(&g_cursor[d], 1);
        g_srcs[pos] = s;
    }
}

// ---------------- Layer-1 GEMM: [N,14] @ [14,1024], 16 nodes per block -----------
// Writes fp32 h (for alpha1) + fp16 copy (for agg1 gather).
#define G1N 16
__global__ __launch_bounds__(256) void gemm1_kernel(const float* __restrict__ x,
                                                    const float* __restrict__ W1,
                                                    float* __restrict__ h) {
    __shared__ float xs[G1N * IN_CH];
    int nb = blockIdx.x * G1N;
    int t = threadIdx.x;
    if (t < G1N * IN_CH) xs[t] = x[nb * IN_CH + t];
    __syncthreads();
#pragma unroll
    for (int j = 0; j < 4; j++) {
        int c = t + j * 256;
        float w[IN_CH];
#pragma unroll
        for (int k = 0; k < IN_CH; k++) w[k] = W1[k * FEAT + c];
        for (int n = 0; n < G1N; n++) {
            float acc = 0.f;
#pragma unroll
            for (int k = 0; k < IN_CH; k++) acc += xs[n * IN_CH + k] * w[k];
            h[(size_t)(nb + n) * FEAT + c] = acc;
            g_h16[(size_t)(nb + n) * FEAT + c] = __float2half_rn(acc);
        }
    }
}

// ---------------- W2 transpose + tf32 pre-round: W2T[n][k] = rna(W2[k][n]) -------
__global__ __launch_bounds__(256) void transpose_kernel(const float* __restrict__ W,
                                                        float* __restrict__ WT) {
    __shared__ float t[32][33];
    int bx = blockIdx.x * 32, by = blockIdx.y * 32;
    int x = bx + threadIdx.x;
    int y = by + threadIdx.y;
#pragma unroll
    for (int j = 0; j < 32; j += 8) t[threadIdx.y + j][threadIdx.x] = W[(size_t)(y + j) * FEAT + x];
    __syncthreads();
    int x2 = by + threadIdx.x;
    int y2 = bx + threadIdx.y;
#pragma unroll
    for (int j = 0; j < 32; j += 8)
        WT[(size_t)(y2 + j) * FEAT + x2] = __uint_as_float(f2tf32(t[threadIdx.x][threadIdx.y + j]));
}

// ---------------- attention logits: als/ald [N,8] ----------------
__global__ __launch_bounds__(256) void alpha_kernel(const float* __restrict__ h,
                                                    const float* __restrict__ asrc,
                                                    const float* __restrict__ adst,
                                                    float* __restrict__ als,
                                                    float* __restrict__ ald) {
    int n = blockIdx.x;
    int t = threadIdx.x, w = t >> 5, lane = t & 31;
    const float* hr = h + (size_t)n * FEAT + w * HID;
    float ss = 0.f, sd = 0.f;
#pragma unroll
    for (int c = lane; c < HID; c += 32) {
        float v = hr[c];
        ss += v * asrc[w * HID + c];
        sd += v * adst[w * HID + c];
    }
#pragma unroll
    for (int off = 16; off; off >>= 1) {
        ss += __shfl_xor_sync(~0u, ss, off);
        sd += __shfl_xor_sync(~0u, sd, off);
    }
    if (lane == 0) { als[n * HEADS + w] = ss; ald[n * HEADS + w] = sd; }
}

// ---------------- fused per-node softmax + aggregate (heads=8, C=128) -----------
// Gathers from the fp16 copy g_h16 (half the L2 traffic), accumulates fp32.
// ROUND: store tf32-rounded output (bit-identical to in-GEMM rounding)
// FUSE3: project through W3 and emit h3/als3/ald3 instead of writing out
template <int ROUND, int FUSE3>
__global__ __launch_bounds__(256) void agg_kernel(const float* __restrict__ als,
                                                  const float* __restrict__ ald,
                                                  const float* __restrict__ bias,
                                                  float* __restrict__ out,
                                                  const float* __restrict__ W3,
                                                  const float* __restrict__ as3,
                                                  const float* __restrict__ ad3) {
    int n = blockIdx.x;
    int t = threadIdx.x, w = t >> 5, lane = t & 31;
    __shared__ float s_alpha[HEADS][32];
    __shared__ int   s_src[32];
    __shared__ float s_p[HEADS][4];
    __shared__ float s_h3[4];

    int start = g_rowptr[n];
    int cnt   = g_rowptr[n + 1] - start;   // self-loop added implicitly at i==cnt

    float aldn = ald[n * HEADS + w];

    // single-pass online softmax stats (strided over edges)
    float m = -1e30f, z = 0.f;
    for (int i = lane; i <= cnt; i += 32) {
        int s = (i < cnt) ? g_srcs[start + i] : n;
        float e = leaky(als[s * HEADS + w] + aldn);
        float mn = fmaxf(m, e);
        z = z * expf(m - mn) + expf(e - mn);
        m = mn;
    }
#pragma unroll
    for (int off = 16; off; off >>= 1) {
        float mo = __shfl_xor_sync(~0u, m, off);
        float zo = __shfl_xor_sync(~0u, z, off);
        float mn = fmaxf(m, mo);
        z = z * expf(m - mn) + zo * expf(mo - mn);
        m = mn;
    }
    float iz = 1.f / (z + 1e-16f);

    // chunked aggregate: per-warp alpha precompute in smem, broadcast consume
    float4 acc = make_float4(0.f, 0.f, 0.f, 0.f);
    const int cbase = w * HID + lane * 4;
    for (int base = 0; base <= cnt; base += 32) {
        int i = base + lane;
        int s = n;
        float a = 0.f;
        if (i <= cnt) {
            if (i < cnt) s = g_srcs[start + i];
            float e = leaky(als[s * HEADS + w] + aldn);
            a = expf(e - m) * iz;
        }
        s_alpha[w][lane] = a;
        if (w == 0) s_src[lane] = s;
        __syncthreads();
        int lim = min(32, cnt + 1 - base);
        for (int j = 0; j < lim; j++) {
            float alpha = s_alpha[w][j];
            int sj = s_src[j];
            uint2 hv = *(const uint2*)&g_h16[(size_t)sj * FEAT + cbase];
            float2 f0 = __half22float2(*reinterpret_cast<const __half2*>(&hv.x));
            float2 f1 = __half22float2(*reinterpret_cast<const __half2*>(&hv.y));
            acc.x += alpha * f0.x; acc.y += alpha * f0.y;
            acc.z += alpha * f1.x; acc.w += alpha * f1.y;
        }
        __syncthreads();
    }
    float4 b4 = *(const float4*)&bias[cbase];
    acc.x = fmaxf(acc.x + b4.x, 0.f);
    acc.y = fmaxf(acc.y + b4.y, 0.f);
    acc.z = fmaxf(acc.z + b4.z, 0.f);
    acc.w = fmaxf(acc.w + b4.w, 0.f);

    if (FUSE3) {
        // project this node's row through W3 [1024,4]; block-reduce
        float p0, p1, p2, p3;
        {
            float4 w0 = *(const float4*)&W3[(cbase + 0) * 4];
            float4 w1 = *(const float4*)&W3[(cbase + 1) * 4];
            float4 w2 = *(const float4*)&W3[(cbase + 2) * 4];
            float4 w3v = *(const float4*)&W3[(cbase + 3) * 4];
            p0 = acc.x * w0.x + acc.y * w1.x + acc.z * w2.x + acc.w * w3v.x;
            p1 = acc.x * w0.y + acc.y * w1.y + acc.z * w2.y + acc.w * w3v.y;
            p2 = acc.x * w0.z + acc.y * w1.z + acc.z * w2.z + acc.w * w3v.z;
            p3 = acc.x * w0.w + acc.y * w1.w + acc.z * w2.w + acc.w * w3v.w;
        }
#pragma unroll
        for (int off = 16; off; off >>= 1) {
            p0 += __shfl_xor_sync(~0u, p0, off);
            p1 += __shfl_xor_sync(~0u, p1, off);
            p2 += __shfl_xor_sync(~0u, p2, off);
            p3 += __shfl_xor_sync(~0u, p3, off);
        }
        if (lane == 0) {
            s_p[w][0] = p0; s_p[w][1] = p1; s_p[w][2] = p2; s_p[w][3] = p3;
        }
        __syncthreads();
        if (t < 4) {
            float v = 0.f;
#pragma unroll
            for (int ww = 0; ww < HEADS; ww++) v += s_p[ww][t];
            g_h3[n * 4 + t] = v;
            s_h3[t] = v;
        }
        __syncthreads();
        if (t == 0) {
            float ss = 0.f, sd = 0.f;
#pragma unroll
            for (int o = 0; o < 4; o++) {
                ss += s_h3[o] * as3[o];
                sd += s_h3[o] * ad3[o];
            }
            g_als3[n] = ss;
            g_ald3[n] = sd;
        }
        return;
    }

    if (ROUND) {
        acc.x = __uint_as_float(f2tf32(acc.x));
        acc.y = __uint_as_float(f2tf32(acc.y));
        acc.z = __uint_as_float(f2tf32(acc.z));
        acc.w = __uint_as_float(f2tf32(acc.w));
    }
    *(float4*)&out[(size_t)n * FEAT + cbase] = acc;
}

// ---------------- tf32 mma.sync GEMM: C[M,1024] = A[M,1024] @ W2, BT[n][k] -------
// Inputs pre-rounded to tf32; mainloop is raw LDS + HMMA only.
// Epilogue also writes the fp16 copy of C for agg2's gather.
#define LDA  36                       // floats per smem row (32 + 4 pad)
#define TBUF (128 * LDA * 4)          // bytes per tile (18432)
#define BUFB (2 * TBUF)               // A+B per stage (36864)
#define NIT  32                       // 1024 / 32

__device__ __forceinline__ void load_tiles_async(
    const float* __restrict__ A, const float* __restrict__ BT,
    uint32_t sA, uint32_t sB, int row0, int n0, int k0, int M, int tid)
{
#pragma unroll
    for (int j = 0; j < 4; j++) {
        int f = tid + j * 256;            // 0..1023
        int r = f >> 3;                   // 0..127
        int c = f & 7;                    // float4 chunk
        uint32_t so = (uint32_t)(r * LDA + c * 4) * 4;
        bool ok = (row0 + r) < M;
        int ar = ok ? (row0 + r) : 0;
        cp_async16(sA + so, A  + (size_t)ar * FEAT + k0 + c * 4, ok);
        cp_async16(sB + so, BT + (size_t)(n0 + r) * FEAT + k0 + c * 4, true);
    }
}

__global__ __launch_bounds__(256) void tf32_gemm_kernel(
    const float* __restrict__ A, const float* __restrict__ BT,
    float* __restrict__ C, int M)
{
    extern __shared__ char dsm[];
    const uint32_t sbase = smem_u32(dsm);
    int tid = threadIdx.x;
    int wid = tid >> 5, lane = tid & 31;
    int grp = lane >> 2, tig = lane & 3;
    int wm = (wid & 1) * 64;
    int wn = (wid >> 1) * 32;
    int row0 = blockIdx.y * 128, n0 = blockIdx.x * 128;

    float acc[4][4][4];
#pragma unroll
    for (int i = 0; i < 4; i++)
#pragma unroll
        for (int j = 0; j < 4; j++)
#pragma unroll
            for (int k = 0; k < 4; k++) acc[i][j][k] = 0.f;

    load_tiles_async(A, BT, sbase, sbase + TBUF, row0, n0, 0, M, tid);
    CP_COMMIT();

    for (int it = 0; it < NIT; it++) {
        CP_WAIT0();
        __syncthreads();
        int cb = it & 1;
        if (it + 1 < NIT) {
            uint32_t nb = sbase + (cb ^ 1) * BUFB;
            load_tiles_async(A, BT, nb, nb + TBUF, row0, n0, (it + 1) * 32, M, tid);
            CP_COMMIT();
        }
        const uint32_t* As = (const uint32_t*)(dsm + cb * BUFB);
        const uint32_t* Bs = (const uint32_t*)(dsm + cb * BUFB + TBUF);
#pragma unroll
        for (int ks = 0; ks < 4; ks++) {
            int kk = ks * 8 + tig;
            uint32_t a[4][4];
#pragma unroll
            for (int mt = 0; mt < 4; mt++) {
                int r0 = wm + mt * 16 + grp;
                a[mt][0] = As[r0 * LDA + kk];
                a[mt][1] = As[(r0 + 8) * LDA + kk];
                a[mt][2] = As[r0 * LDA + kk + 4];
                a[mt][3] = As[(r0 + 8) * LDA + kk + 4];
            }
#pragma unroll
            for (int nt = 0; nt < 4; nt++) {
                int rn = wn + nt * 8 + grp;
                uint32_t b0 = Bs[rn * LDA + kk];
                uint32_t b1 = Bs[rn * LDA + kk + 4];
#pragma unroll
                for (int mt = 0; mt < 4; mt++) mma_tf32(acc[mt][nt], a[mt], b0, b1);
            }
        }
        __syncthreads();
    }

    // epilogue: fp32 C + fp16 copy
#pragma unroll
    for (int mt = 0; mt < 4; mt++) {
        int gr = row0 + wm + mt * 16 + grp;
#pragma unroll
        for (int nt = 0; nt < 4; nt++) {
            int gc = n0 + wn + nt * 8 + 2 * tig;
            if (gr < M) {
                float2 v0 = make_float2(acc[mt][nt][0], acc[mt][nt][1]);
                *(float2*)&C[(size_t)gr * FEAT + gc] = v0;
                *(__half2*)&g_h16[(size_t)gr * FEAT + gc] = __floats2half2_rn(v0.x, v0.y);
            }
            if (gr + 8 < M) {
                float2 v1 = make_float2(acc[mt][nt][2], acc[mt][nt][3]);
                *(float2*)&C[(size_t)(gr + 8) * FEAT + gc] = v1;
                *(__half2*)&g_h16[(size_t)(gr + 8) * FEAT + gc] = __floats2half2_rn(v1.x, v1.y);
            }
        }
    }
}

// ---------------- layer-3 aggregation (warp per node, 1 head, C=4) --------------
__global__ __launch_bounds__(256) void agg3_kernel(const float* __restrict__ b3,
                                                   float* __restrict__ out) {
    int n = (blockIdx.x * blockDim.x + threadIdx.x) >> 5;
    int lane = threadIdx.x & 31;
    if (n >= N_NODES) return;
    int start = g_rowptr[n];
    int cnt   = g_rowptr[n + 1] - start;
    float aldn = g_ald3[n];
    float mx = -1e30f;
    for (int i = lane; i <= cnt; i += 32) {
        int s = (i < cnt) ? g_srcs[start + i] : n;
        mx = fmaxf(mx, leaky(g_als3[s] + aldn));
    }
#pragma unroll
    for (int off = 16; off; off >>= 1) mx = fmaxf(mx, __shfl_xor_sync(~0u, mx, off));
    float z = 0.f;
    float c0 = 0.f, c1 = 0.f, c2 = 0.f, c3 = 0.f;
    for (int i = lane; i <= cnt; i += 32) {
        int s = (i < cnt) ? g_srcs[start + i] : n;
        float e = leaky(g_als3[s] + aldn);
        float ex = expf(e - mx);
        z += ex;
        c0 += ex * g_h3[s * 4 + 0];
        c1 += ex * g_h3[s * 4 + 1];
        c2 += ex * g_h3[s * 4 + 2];
        c3 += ex * g_h3[s * 4 + 3];
    }
#pragma unroll
    for (int off = 16; off; off >>= 1) {
        z  += __shfl_xor_sync(~0u, z, off);
        c0 += __shfl_xor_sync(~0u, c0, off);
        c1 += __shfl_xor_sync(~0u, c1, off);
        c2 += __shfl_xor_sync(~0u, c2, off);
        c3 += __shfl_xor_sync(~0u, c3, off);
    }
    float iz = 1.f / (z + 1e-16f);
    if (lane == 0) {
        out[n * 4 + 0] = fmaxf(c0 * iz + b3[0], 0.f);
        out[n * 4 + 1] = fmaxf(c1 * iz + b3[1], 0.f);
        out[n * 4 + 2] = fmaxf(c2 * iz + b3[2], 0.f);
        out[n * 4 + 3] = fmaxf(c3 * iz + b3[3], 0.f);
    }
}

// ---------------- launch ----------------
extern "C" void kernel_launch(void* const* d_in, const int* in_sizes, int n_in,
                              void* d_out, int out_size) {
    const float* x      = (const float*)d_in[0];
    const void*  eidx   = d_in[1];
    const float* W1     = (const float*)d_in[2];
    const float* a_src1 = (const float*)d_in[3];
    const float* a_dst1 = (const float*)d_in[4];
    const float* b1     = (const float*)d_in[5];
    const float* W2     = (const float*)d_in[6];
    const float* a_src2 = (const float*)d_in[7];
    const float* a_dst2 = (const float*)d_in[8];
    const float* b2     = (const float*)d_in[9];
    const float* W3     = (const float*)d_in[10];
    const float* a_src3 = (const float*)d_in[11];
    const float* a_dst3 = (const float*)d_in[12];
    const float* b3     = (const float*)d_in[13];
    float* out = (float*)d_out;

    float* bufA; cudaGetSymbolAddress((void**)&bufA, g_bufA);
    float* bufB; cudaGetSymbolAddress((void**)&bufB, g_bufB);
    float* w2t;  cudaGetSymbolAddress((void**)&w2t,  g_W2T);
    float* als;  cudaGetSymbolAddress((void**)&als,  g_als);
    float* ald;  cudaGetSymbolAddress((void**)&ald,  g_ald);

    static bool attr_set = false;
    if (!attr_set) {
        cudaFuncSetAttribute(tf32_gemm_kernel,
                             cudaFuncAttributeMaxDynamicSharedMemorySize, 2 * BUFB);
        attr_set = true;
    }

    // CSR build (detect fused into zero)
    zero_kernel<<<(N_NODES + 255) / 256, 256>>>((const int*)eidx);
    count_kernel<<<(E_EDGES + 255) / 256, 256>>>(eidx);
    scan_kernel<<<1, 1024>>>();
    scatter_kernel<<<(E_EDGES + 255) / 256, 256>>>(eidx);

    // layer 1 (writes fp32 h + fp16 copy)
    gemm1_kernel<<<N_NODES / G1N, 256>>>(x, W1, bufA);
    alpha_kernel<<<N_NODES, 256>>>(bufA, a_src1, a_dst1, als, ald);
    agg_kernel<1, 0><<<N_NODES, 256>>>(als, ald, b1, bufB,
                                       nullptr, nullptr, nullptr);

    // layer 2 (tf32 mma.sync GEMM, pre-rounded inputs; epilogue writes fp16 copy)
    transpose_kernel<<<dim3(32, 32), dim3(32, 8)>>>(W2, w2t);
    dim3 g2(FEAT / 128, (N_NODES + 127) / 128);
    tf32_gemm_kernel<<<g2, 256, 2 * BUFB>>>(bufB, w2t, bufA, N_NODES);
    alpha_kernel<<<N_NODES, 256>>>(bufA, a_src2, a_dst2, als, ald);
    // layer-2 aggregate with fused layer-3 projection (no bufB write, no gemm3)
    agg_kernel<0, 1><<<N_NODES, 256>>>(als, ald, b2, nullptr,
                                       W3, a_src3, a_dst3);

    // layer 3 aggregation
    agg3_kernel<<<(N_NODES * 32 + 255) / 256, 256>>>(b3, out);
}

// round 15
// speedup vs baseline: 1.3770x; 1.2400x over previous
#include <cuda_runtime.h>
#include <cuda_bf16.h>
#include <cuda_fp16.h>
#include <cstdint>

#define N_NODES 10000
#define E_EDGES 160000
#define IN_CH   14
#define HID     128
#define HEADS   8
#define OUT_CH  4
#define FEAT    (HEADS*HID)   // 1024

// ---------------- scratch (static device memory; no allocations) ----------------
__device__ float  g_bufA[(size_t)N_NODES * FEAT];   // fp32 h (layer1, then layer2)
__device__ __half g_h16[(size_t)N_NODES * FEAT];    // fp16 copy of h for agg gather
__device__ __half g_hB16[(size_t)N_NODES * FEAT];   // fp16 agg1 output (GEMM A input)
__device__ __half g_W2T16[(size_t)FEAT * FEAT];     // fp16 W2 transposed (GEMM B input)
__device__ float  g_als[N_NODES * HEADS];
__device__ float  g_ald[N_NODES * HEADS];
__device__ float  g_h3[N_NODES * OUT_CH];
__device__ float  g_als3[N_NODES];
__device__ float  g_ald3[N_NODES];
__device__ int    g_deg[N_NODES];       // zero-initialized; re-zeroed by agg3 tail
__device__ int    g_cursor[N_NODES];    // ditto
__device__ int    g_rowptr[N_NODES + 1];
__device__ int    g_srcs[E_EDGES];
__device__ int    g_is64;

// ---------------- small PTX helpers ----------------
__device__ __forceinline__ uint32_t smem_u32(const void* p) {
    uint32_t a;
    asm("{ .reg .u64 t; cvta.to.shared.u64 t, %1; cvt.u32.u64 %0, t; }" : "=r"(a) : "l"(p));
    return a;
}

__device__ __forceinline__ void cp_async16(uint32_t s, const void* g, bool pred) {
    int sz = pred ? 16 : 0;
    asm volatile("cp.async.cg.shared.global [%0], [%1], 16, %2;\n"
                 :: "r"(s), "l"(g), "r"(sz) : "memory");
}
#define CP_COMMIT()  asm volatile("cp.async.commit_group;" ::: "memory")
#define CP_WAIT0()   asm volatile("cp.async.wait_group 0;" ::: "memory")

__device__ __forceinline__ void mma_f16(float* c, const uint32_t* a, uint32_t b0, uint32_t b1) {
    asm volatile(
        "mma.sync.aligned.m16n8k16.row.col.f32.f16.f16.f32 "
        "{%0,%1,%2,%3}, {%4,%5,%6,%7}, {%8,%9}, {%0,%1,%2,%3};"
        : "+f"(c[0]), "+f"(c[1]), "+f"(c[2]), "+f"(c[3])
        : "r"(a[0]), "r"(a[1]), "r"(a[2]), "r"(a[3]), "r"(b0), "r"(b1));
}

__device__ __forceinline__ float leaky(float e) {
    return e > 0.f ? e : 0.2f * e;
}

// ---------------- edge index access (int32 vs int64 detected at runtime) --------
__device__ __forceinline__ int edge_val(const void* idx, int is64, long i) {
    if (is64) return (int)((const long long*)idx)[i];
    return ((const int*)idx)[i];
}

// ---------------- CSR build ----------------
__global__ void count_kernel(const void* idx) {
    int e = blockIdx.x * blockDim.x + threadIdx.x;
    if (e < E_EDGES) {
        int f = g_is64;
        int d = edge_val(idx, f, (long)E_EDGES + e);
        atomicAdd(&g_deg[d], 1);
    }
}

// shuffle-based scan: 1024 threads, 10 elems/thread, 2 barriers
__global__ void scan_kernel() {
    __shared__ int wsum[32];
    int t = threadIdx.x, lane = t & 31, w = t >> 5;
    const int CH = (N_NODES + 1023) / 1024;  // 10
    int base = t * CH;
    int s = 0;
#pragma unroll
    for (int i = 0; i < CH; i++) {
        int idx = base + i;
        if (idx < N_NODES) s += g_deg[idx];
    }
    int v = s;
#pragma unroll
    for (int off = 1; off < 32; off <<= 1) {
        int u = __shfl_up_sync(~0u, v, off);
        if (lane >= off) v += u;
    }
    if (lane == 31) wsum[w] = v;
    __syncthreads();
    if (w == 0) {
        int x = wsum[lane];
#pragma unroll
        for (int off = 1; off < 32; off <<= 1) {
            int u = __shfl_up_sync(~0u, x, off);
            if (lane >= off) x += u;
        }
        wsum[lane] = x;
    }
    __syncthreads();
    int excl = v - s + (w > 0 ? wsum[w - 1] : 0);
    int run = excl;
#pragma unroll
    for (int i = 0; i < CH; i++) {
        int idx = base + i;
        if (idx < N_NODES) { g_rowptr[idx] = run; run += g_deg[idx]; }
    }
    if (t == 1023) g_rowptr[N_NODES] = run;
}

__global__ void scatter_kernel(const void* idx) {
    int e = blockIdx.x * blockDim.x + threadIdx.x;
    if (e < E_EDGES) {
        int f = g_is64;
        int s = edge_val(idx, f, e);
        int d = edge_val(idx, f, (long)E_EDGES + e);
        int pos = g_rowptr[d] + atomicAdd(&g_cursor[d], 1);
        g_srcs[pos] = s;
    }
}

// ---------------- prep kernel: gemm1 (625 blocks) + W2 transpose (1024 blocks) ---
// Also performs edge-width detection (block 0).
#define G1N 16
#define PREP_G1_BLOCKS (N_NODES / G1N)          // 625
#define PREP_TR_BLOCKS (32 * 32)                // 1024
__global__ __launch_bounds__(256) void prep_kernel(const float* __restrict__ x,
                                                   const float* __restrict__ W1,
                                                   const float* __restrict__ W2,
                                                   const int* __restrict__ eidx32,
                                                   float* __restrict__ h) {
    int t = threadIdx.x;
    if (blockIdx.x == 0 && t == 0) {
        int is64 = 1;
        for (int k = 0; k < 64; k++) {
            if (eidx32[2*k + 1] != 0) { is64 = 0; break; }
        }
        g_is64 = is64;
    }
    if (blockIdx.x < PREP_G1_BLOCKS) {
        // ---- layer-1 GEMM: [16,14] @ [14,1024], fp32 + fp16 copy ----
        __shared__ float xs[G1N * IN_CH];
        int nb = blockIdx.x * G1N;
        if (t < G1N * IN_CH) xs[t] = x[nb * IN_CH + t];
        __syncthreads();
#pragma unroll
        for (int j = 0; j < 4; j++) {
            int c = t + j * 256;
            float w[IN_CH];
#pragma unroll
            for (int k = 0; k < IN_CH; k++) w[k] = W1[k * FEAT + c];
            for (int n = 0; n < G1N; n++) {
                float acc = 0.f;
#pragma unroll
                for (int k = 0; k < IN_CH; k++) acc += xs[n * IN_CH + k] * w[k];
                h[(size_t)(nb + n) * FEAT + c] = acc;
                g_h16[(size_t)(nb + n) * FEAT + c] = __float2half_rn(acc);
            }
        }
    } else {
        // ---- W2 transpose to fp16: W2T16[n][k] = rn(W2[k][n]) ----
        __shared__ float tt[32][33];
        int tb = blockIdx.x - PREP_G1_BLOCKS;
        int bx = (tb & 31) * 32, by = (tb >> 5) * 32;
        int tx = t & 31, ty = t >> 5;   // 32 x 8
        int xg = bx + tx;
#pragma unroll
        for (int j = 0; j < 32; j += 8) tt[ty + j][tx] = W2[(size_t)(by + ty + j) * FEAT + xg];
        __syncthreads();
        int x2 = by + tx;
        int y2 = bx + ty;
#pragma unroll
        for (int j = 0; j < 32; j += 8)
            g_W2T16[(size_t)(y2 + j) * FEAT + x2] = __float2half_rn(tt[tx][ty + j]);
    }
}

// ---------------- attention logits: als/ald [N,8] ----------------
__global__ __launch_bounds__(256) void alpha_kernel(const float* __restrict__ h,
                                                    const float* __restrict__ asrc,
                                                    const float* __restrict__ adst,
                                                    float* __restrict__ als,
                                                    float* __restrict__ ald) {
    int n = blockIdx.x;
    int t = threadIdx.x, w = t >> 5, lane = t & 31;
    const float* hr = h + (size_t)n * FEAT + w * HID;
    float ss = 0.f, sd = 0.f;
#pragma unroll
    for (int c = lane; c < HID; c += 32) {
        float v = hr[c];
        ss += v * asrc[w * HID + c];
        sd += v * adst[w * HID + c];
    }
#pragma unroll
    for (int off = 16; off; off >>= 1) {
        ss += __shfl_xor_sync(~0u, ss, off);
        sd += __shfl_xor_sync(~0u, sd, off);
    }
    if (lane == 0) { als[n * HEADS + w] = ss; ald[n * HEADS + w] = sd; }
}

// ---------------- fused per-node softmax + aggregate (heads=8, C=128) -----------
// Gathers from fp16 g_h16, accumulates fp32.
// MODE 0: write fp16 output to g_hB16 (layer-1 -> GEMM input)
// MODE 1: fuse layer-3 projection, emit h3/als3/ald3 (layer-2)
template <int MODE>
__global__ __launch_bounds__(256) void agg_kernel(const float* __restrict__ als,
                                                  const float* __restrict__ ald,
                                                  const float* __restrict__ bias,
                                                  const float* __restrict__ W3,
                                                  const float* __restrict__ as3,
                                                  const float* __restrict__ ad3) {
    int n = blockIdx.x;
    int t = threadIdx.x, w = t >> 5, lane = t & 31;
    __shared__ float s_alpha[HEADS][32];
    __shared__ int   s_src[32];
    __shared__ float s_p[HEADS][4];
    __shared__ float s_h3[4];

    int start = g_rowptr[n];
    int cnt   = g_rowptr[n + 1] - start;   // self-loop added implicitly at i==cnt

    float aldn = ald[n * HEADS + w];

    // single-pass online softmax stats (strided over edges)
    float m = -1e30f, z = 0.f;
    for (int i = lane; i <= cnt; i += 32) {
        int s = (i < cnt) ? g_srcs[start + i] : n;
        float e = leaky(als[s * HEADS + w] + aldn);
        float mn = fmaxf(m, e);
        z = z * expf(m - mn) + expf(e - mn);
        m = mn;
    }
#pragma unroll
    for (int off = 16; off; off >>= 1) {
        float mo = __shfl_xor_sync(~0u, m, off);
        float zo = __shfl_xor_sync(~0u, z, off);
        float mn = fmaxf(m, mo);
        z = z * expf(m - mn) + zo * expf(mo - mn);
        m = mn;
    }
    float iz = 1.f / (z + 1e-16f);

    // chunked aggregate: per-warp alpha precompute in smem, broadcast consume
    float4 acc = make_float4(0.f, 0.f, 0.f, 0.f);
    const int cbase = w * HID + lane * 4;
    for (int base = 0; base <= cnt; base += 32) {
        int i = base + lane;
        int s = n;
        float a = 0.f;
        if (i <= cnt) {
            if (i < cnt) s = g_srcs[start + i];
            float e = leaky(als[s * HEADS + w] + aldn);
            a = expf(e - m) * iz;
        }
        s_alpha[w][lane] = a;
        if (w == 0) s_src[lane] = s;
        __syncthreads();
        int lim = min(32, cnt + 1 - base);
        for (int j = 0; j < lim; j++) {
            float alpha = s_alpha[w][j];
            int sj = s_src[j];
            uint2 hv = *(const uint2*)&g_h16[(size_t)sj * FEAT + cbase];
            float2 f0 = __half22float2(*reinterpret_cast<const __half2*>(&hv.x));
            float2 f1 = __half22float2(*reinterpret_cast<const __half2*>(&hv.y));
            acc.x += alpha * f0.x; acc.y += alpha * f0.y;
            acc.z += alpha * f1.x; acc.w += alpha * f1.y;
        }
        __syncthreads();
    }
    float4 b4 = *(const float4*)&bias[cbase];
    acc.x = fmaxf(acc.x + b4.x, 0.f);
    acc.y = fmaxf(acc.y + b4.y, 0.f);
    acc.z = fmaxf(acc.z + b4.z, 0.f);
    acc.w = fmaxf(acc.w + b4.w, 0.f);

    if (MODE == 1) {
        // project this node's row through W3 [1024,4]; block-reduce
        float p0, p1, p2, p3;
        {
            float4 w0 = *(const float4*)&W3[(cbase + 0) * 4];
            float4 w1 = *(const float4*)&W3[(cbase + 1) * 4];
            float4 w2 = *(const float4*)&W3[(cbase + 2) * 4];
            float4 w3v = *(const float4*)&W3[(cbase + 3) * 4];
            p0 = acc.x * w0.x + acc.y * w1.x + acc.z * w2.x + acc.w * w3v.x;
            p1 = acc.x * w0.y + acc.y * w1.y + acc.z * w2.y + acc.w * w3v.y;
            p2 = acc.x * w0.z + acc.y * w1.z + acc.z * w2.z + acc.w * w3v.z;
            p3 = acc.x * w0.w + acc.y * w1.w + acc.z * w2.w + acc.w * w3v.w;
        }
#pragma unroll
        for (int off = 16; off; off >>= 1) {
            p0 += __shfl_xor_sync(~0u, p0, off);
            p1 += __shfl_xor_sync(~0u, p1, off);
            p2 += __shfl_xor_sync(~0u, p2, off);
            p3 += __shfl_xor_sync(~0u, p3, off);
        }
        if (lane == 0) {
            s_p[w][0] = p0; s_p[w][1] = p1; s_p[w][2] = p2; s_p[w][3] = p3;
        }
        __syncthreads();
        if (t < 4) {
            float v = 0.f;
#pragma unroll
            for (int ww = 0; ww < HEADS; ww++) v += s_p[ww][t];
            g_h3[n * 4 + t] = v;
            s_h3[t] = v;
        }
        __syncthreads();
        if (t == 0) {
            float ss = 0.f, sd = 0.f;
#pragma unroll
            for (int o = 0; o < 4; o++) {
                ss += s_h3[o] * as3[o];
                sd += s_h3[o] * ad3[o];
            }
            g_als3[n] = ss;
            g_ald3[n] = sd;
        }
    } else {
        // fp16 output for the fp16 tensor-core GEMM
        __half2 o0 = __floats2half2_rn(acc.x, acc.y);
        __half2 o1 = __floats2half2_rn(acc.z, acc.w);
        uint2 pk;
        pk.x = *reinterpret_cast<uint32_t*>(&o0);
        pk.y = *reinterpret_cast<uint32_t*>(&o1);
        *(uint2*)&g_hB16[(size_t)n * FEAT + cbase] = pk;
    }
}

// ---------------- fp16 mma.sync GEMM: C[M,1024] = A16[M,1024] @ W2 (BT16[n][k]) --
// CTA 128x128, BK=32, 8 warps each 64x32, double-buffered cp.async pipeline.
#define LDH   40                      // halves per smem row (32 + 8 pad)
#define TBUF16 (128 * LDH * 2)        // bytes per tile (10240)
#define STG16  (2 * TBUF16)           // A+B per stage (20480)
#define NIT   32                      // 1024 / 32

__device__ __forceinline__ void load_tiles16(
    const __half* __restrict__ A, const __half* __restrict__ BT,
    uint32_t sA, uint32_t sB, int row0, int n0, int k0, int M, int tid)
{
#pragma unroll
    for (int j = 0; j < 2; j++) {
        int f = tid + j * 256;            // 0..511
        int r = f >> 2;                   // 0..127
        int c = f & 3;                    // 16B chunk (8 halves)
        uint32_t so = (uint32_t)(r * LDH + c * 8) * 2;
        bool ok = (row0 + r) < M;
        int ar = ok ? (row0 + r) : 0;
        cp_async16(sA + so, A  + (size_t)ar * FEAT + k0 + c * 8, ok);
        cp_async16(sB + so, BT + (size_t)(n0 + r) * FEAT + k0 + c * 8, true);
    }
}

__global__ __launch_bounds__(256) void f16_gemm_kernel(
    const __half* __restrict__ A, const __half* __restrict__ BT,
    float* __restrict__ C, int M)
{
    extern __shared__ char dsm[];
    const uint32_t sbase = smem_u32(dsm);
    int tid = threadIdx.x;
    int wid = tid >> 5, lane = tid & 31;
    int grp = lane >> 2, tig = lane & 3;
    int wm = (wid & 1) * 64;
    int wn = (wid >> 1) * 32;
    int row0 = blockIdx.y * 128, n0 = blockIdx.x * 128;

    float acc[4][4][4];
#pragma unroll
    for (int i = 0; i < 4; i++)
#pragma unroll
        for (int j = 0; j < 4; j++)
#pragma unroll
            for (int k = 0; k < 4; k++) acc[i][j][k] = 0.f;

    load_tiles16(A, BT, sbase, sbase + TBUF16, row0, n0, 0, M, tid);
    CP_COMMIT();

    for (int it = 0; it < NIT; it++) {
        CP_WAIT0();
        __syncthreads();
        int cb = it & 1;
        if (it + 1 < NIT) {
            uint32_t nb = sbase + (cb ^ 1) * STG16;
            load_tiles16(A, BT, nb, nb + TBUF16, row0, n0, (it + 1) * 32, M, tid);
            CP_COMMIT();
        }
        const uint32_t* As2 = (const uint32_t*)(dsm + cb * STG16);
        const uint32_t* Bs2 = (const uint32_t*)(dsm + cb * STG16 + TBUF16);
#pragma unroll
        for (int ks = 0; ks < 2; ks++) {
            int kb = ks * 8 + tig;        // half2 index within row
            uint32_t a[4][4];
#pragma unroll
            for (int mt = 0; mt < 4; mt++) {
                int r0 = wm + mt * 16 + grp;
                a[mt][0] = As2[r0 * (LDH/2) + kb];
                a[mt][1] = As2[(r0 + 8) * (LDH/2) + kb];
                a[mt][2] = As2[r0 * (LDH/2) + kb + 4];
                a[mt][3] = As2[(r0 + 8) * (LDH/2) + kb + 4];
            }
#pragma unroll
            for (int nt = 0; nt < 4; nt++) {
                int rn = wn + nt * 8 + grp;
                uint32_t b0 = Bs2[rn * (LDH/2) + kb];
                uint32_t b1 = Bs2[rn * (LDH/2) + kb + 4];
#pragma unroll
                for (int mt = 0; mt < 4; mt++) mma_f16(acc[mt][nt], a[mt], b0, b1);
            }
        }
        __syncthreads();
    }

    // epilogue: fp32 C + fp16 copy
#pragma unroll
    for (int mt = 0; mt < 4; mt++) {
        int gr = row0 + wm + mt * 16 + grp;
#pragma unroll
        for (int nt = 0; nt < 4; nt++) {
            int gc = n0 + wn + nt * 8 + 2 * tig;
            if (gr < M) {
                float2 v0 = make_float2(acc[mt][nt][0], acc[mt][nt][1]);
                *(float2*)&C[(size_t)gr * FEAT + gc] = v0;
                *(__half2*)&g_h16[(size_t)gr * FEAT + gc] = __floats2half2_rn(v0.x, v0.y);
            }
            if (gr + 8 < M) {
                float2 v1 = make_float2(acc[mt][nt][2], acc[mt][nt][3]);
                *(float2*)&C[(size_t)(gr + 8) * FEAT + gc] = v1;
                *(__half2*)&g_h16[(size_t)(gr + 8) * FEAT + gc] = __floats2half2_rn(v1.x, v1.y);
            }
        }
    }
}

// ---------------- layer-3 aggregation + deg/cursor re-zero for next replay ------
__global__ __launch_bounds__(256) void agg3_kernel(const float* __restrict__ b3,
                                                   float* __restrict__ out) {
    // re-zero CSR scratch for the next graph replay (idempotent on first call)
    {
        int gid = blockIdx.x * blockDim.x + threadIdx.x;
        if (gid < N_NODES) { g_deg[gid] = 0; g_cursor[gid] = 0; }
    }
    int n = (blockIdx.x * blockDim.x + threadIdx.x) >> 5;
    int lane = threadIdx.x & 31;
    if (n >= N_NODES) return;
    int start = g_rowptr[n];
    int cnt   = g_rowptr[n + 1] - start;
    float aldn = g_ald3[n];
    float mx = -1e30f;
    for (int i = lane; i <= cnt; i += 32) {
        int s = (i < cnt) ? g_srcs[start + i] : n;
        mx = fmaxf(mx, leaky(g_als3[s] + aldn));
    }
#pragma unroll
    for (int off = 16; off; off >>= 1) mx = fmaxf(mx, __shfl_xor_sync(~0u, mx, off));
    float z = 0.f;
    float c0 = 0.f, c1 = 0.f, c2 = 0.f, c3 = 0.f;
    for (int i = lane; i <= cnt; i += 32) {
        int s = (i < cnt) ? g_srcs[start + i] : n;
        float e = leaky(g_als3[s] + aldn);
        float ex = expf(e - mx);
        z += ex;
        c0 += ex * g_h3[s * 4 + 0];
        c1 += ex * g_h3[s * 4 + 1];
        c2 += ex * g_h3[s * 4 + 2];
        c3 += ex * g_h3[s * 4 + 3];
    }
#pragma unroll
    for (int off = 16; off; off >>= 1) {
        z  += __shfl_xor_sync(~0u, z, off);
        c0 += __shfl_xor_sync(~0u, c0, off);
        c1 += __shfl_xor_sync(~0u, c1, off);
        c2 += __shfl_xor_sync(~0u, c2, off);
        c3 += __shfl_xor_sync(~0u, c3, off);
    }
    float iz = 1.f / (z + 1e-16f);
    if (lane == 0) {
        out[n * 4 + 0] = fmaxf(c0 * iz + b3[0], 0.f);
        out[n * 4 + 1] = fmaxf(c1 * iz + b3[1], 0.f);
        out[n * 4 + 2] = fmaxf(c2 * iz + b3[2], 0.f);
        out[n * 4 + 3] = fmaxf(c3 * iz + b3[3], 0.f);
    }
}

// ---------------- launch ----------------
extern "C" void kernel_launch(void* const* d_in, const int* in_sizes, int n_in,
                              void* d_out, int out_size) {
    const float* x      = (const float*)d_in[0];
    const void*  eidx   = d_in[1];
    const float* W1     = (const float*)d_in[2];
    const float* a_src1 = (const float*)d_in[3];
    const float* a_dst1 = (const float*)d_in[4];
    const float* b1     = (const float*)d_in[5];
    const float* W2     = (const float*)d_in[6];
    const float* a_src2 = (const float*)d_in[7];
    const float* a_dst2 = (const float*)d_in[8];
    const float* b2     = (const float*)d_in[9];
    const float* W3     = (const float*)d_in[10];
    const float* a_src3 = (const float*)d_in[11];
    const float* a_dst3 = (const float*)d_in[12];
    const float* b3     = (const float*)d_in[13];
    float* out = (float*)d_out;

    float*  bufA;  cudaGetSymbolAddress((void**)&bufA,  g_bufA);
    __half* hB16;  cudaGetSymbolAddress((void**)&hB16,  g_hB16);
    __half* w2t16; cudaGetSymbolAddress((void**)&w2t16, g_W2T16);
    float*  als;   cudaGetSymbolAddress((void**)&als,   g_als);
    float*  ald;   cudaGetSymbolAddress((void**)&ald,   g_ald);

    static bool attr_set = false;
    if (!attr_set) {
        cudaFuncSetAttribute(f16_gemm_kernel,
                             cudaFuncAttributeMaxDynamicSharedMemorySize, 2 * STG16);
        attr_set = true;
    }

    // prep: gemm1 + W2 transpose(fp16) + edge-width detect  (1 launch)
    prep_kernel<<<PREP_G1_BLOCKS + PREP_TR_BLOCKS, 256>>>(x, W1, W2,
                                                          (const int*)eidx, bufA);

    // CSR build (deg/cursor pre-zeroed: static init on call 1, agg3 tail after)
    count_kernel<<<(E_EDGES + 255) / 256, 256>>>(eidx);
    scan_kernel<<<1, 1024>>>();
    scatter_kernel<<<(E_EDGES + 255) / 256, 256>>>(eidx);

    // layer 1
    alpha_kernel<<<N_NODES, 256>>>(bufA, a_src1, a_dst1, als, ald);
    agg_kernel<0><<<N_NODES, 256>>>(als, ald, b1, nullptr, nullptr, nullptr);

    // layer 2 (fp16 tensor-core GEMM)
    dim3 g2(FEAT / 128, (N_NODES + 127) / 128);
    f16_gemm_kernel<<<g2, 256, 2 * STG16>>>(hB16, w2t16, bufA, N_NODES);
    alpha_kernel<<<N_NODES, 256>>>(bufA, a_src2, a_dst2, als, ald);
    agg_kernel<1><<<N_NODES, 256>>>(als, ald, b2, W3, a_src3, a_dst3);

    // layer 3 aggregation (+ scratch re-zero for next replay)
    agg3_kernel<<<(N_NODES * 32 + 255) / 256, 256>>>(b3, out);
}